// round 14
// baseline (speedup 1.0000x reference)
#include <cuda_runtime.h>
#include <cuda_bf16.h>
#include <cstdint>

#define D            128
#define S            16
#define NREL         64
#define WARPS_PB     16
#define ITEM_TILE    2
#define ITEMS_PB     32
#define BLOCK_THREADS 512

#define HSTRIDE      136    // bf16 stride (Wt/Rt/Xs/Ms/Us)
#define FSTRIDE      132    // fp32 stride (Hs)
#define SCSTRIDE     68     // fp32 stride (SC)

// smem layout (bytes):
//   Wt bf16 [128][136] = 34816   (reused as Hs fp32 [32][132] in epilogue)
//   Rt bf16 [64][136]  = 17408
//   SC fp32 [32][68]   = 8704
//   Xs bf16 [32][136]  = 8704    (first used as Us: U tile for score GEMM)
//   Ms bf16 [32][136]  = 8704
#define OFF_WT  0
#define OFF_RT  34816
#define OFF_SC  (34816 + 17408)
#define OFF_XS  (OFF_SC + 8704)
#define OFF_MS  (OFF_XS + 8704)
#define SMEM_BYTES (OFF_MS + 8704)          // 78336 -> 2 blocks/SM

__device__ __forceinline__ void mma_bf16(float acc[4], const uint32_t a[4],
                                         const uint32_t b[2]) {
    asm("mma.sync.aligned.m16n8k16.row.col.f32.bf16.bf16.f32 "
        "{%0,%1,%2,%3}, {%4,%5,%6,%7}, {%8,%9}, {%0,%1,%2,%3};"
        : "+f"(acc[0]), "+f"(acc[1]), "+f"(acc[2]), "+f"(acc[3])
        : "r"(a[0]), "r"(a[1]), "r"(a[2]), "r"(a[3]),
          "r"(b[0]), "r"(b[1]));
}

__device__ __forceinline__ uint32_t pack_bf16x2(float lo, float hi) {
    __nv_bfloat162 v = __floats2bfloat162_rn(lo, hi);
    return *(uint32_t*)&v;
}

__global__ __launch_bounds__(BLOCK_THREADS, 2)     // 32 warps/SM
void kgcn_kernel(const int* __restrict__ u,
                 const int* __restrict__ v,
                 const int* __restrict__ adj_ent,
                 const int* __restrict__ adj_rel,
                 const float* __restrict__ usr,
                 const float* __restrict__ ent,
                 const float* __restrict__ rel,
                 const float* __restrict__ W,
                 const float* __restrict__ bias,
                 float* __restrict__ out,
                 int B)
{
    extern __shared__ char sm[];
    __nv_bfloat16* Wt = (__nv_bfloat16*)(sm + OFF_WT);
    __nv_bfloat16* Rt = (__nv_bfloat16*)(sm + OFF_RT);
    float*         SC = (float*)        (sm + OFF_SC);
    __nv_bfloat16* Xs = (__nv_bfloat16*)(sm + OFF_XS);
    __nv_bfloat16* Ms = (__nv_bfloat16*)(sm + OFF_MS);
    float*         Hs = (float*)        (sm + OFF_WT);

    const int tid  = threadIdx.x;
    const int lane = tid & 31;
    const int wid  = tid >> 5;
    const int g    = lane >> 2;
    const int tq   = lane & 3;

    // ---- stage Wt (transposed) and Rt (row-major) as bf16 ----
    for (int idx = tid; idx < D * D; idx += BLOCK_THREADS) {
        const int k = idx >> 7;
        const int n = idx & 127;
        Wt[n * HSTRIDE + k] = __float2bfloat16(W[idx]);
    }
    for (int idx = tid; idx < NREL * D; idx += BLOCK_THREADS) {
        const int r = idx >> 7;
        const int k = idx & 127;
        Rt[r * HSTRIDE + k] = __float2bfloat16(rel[idx]);
    }

    const int base = (blockIdx.x * WARPS_PB + wid) * ITEM_TILE;

    const float4* usr4 = (const float4*)usr;
    const float4* ent4 = (const float4*)ent;
    const int4*   adjE4 = (const int4*)adj_ent;
    const int4*   adjR4 = (const int4*)adj_rel;

    // ---- stage U tile (bf16) into Xs (Us alias) ----
    #pragma unroll
    for (int t = 0; t < ITEM_TILE; t++) {
        const int item = base + t;
        const int cit  = item < B ? item : (B - 1);
        const float4 uex = usr4[(size_t)u[cit] * 32 + lane];
        const int row = wid * ITEM_TILE + t;
        uint32_t* up = (uint32_t*)(Xs + row * HSTRIDE + lane * 4);
        up[0] = pack_bf16x2(uex.x, uex.y);
        up[1] = pack_bf16x2(uex.z, uex.w);
    }

    // prefetch both items' v-indices early (overlaps the pointer chase)
    int iv_[ITEM_TILE];
    #pragma unroll
    for (int t = 0; t < ITEM_TILE; t++) {
        const int item = base + t;
        const int cit  = item < B ? item : (B - 1);
        iv_[t] = v[cit];
    }
    __syncthreads();

    // ---- score GEMM: SC[32x64] = U[32x128] @ Rt^T, warps 0-7 ----
    if (wid < 8) {
        const int nc0 = wid * 8;
        float sacc[2][4];
        #pragma unroll
        for (int mt = 0; mt < 2; mt++) {
            sacc[mt][0] = 0.f; sacc[mt][1] = 0.f;
            sacc[mt][2] = 0.f; sacc[mt][3] = 0.f;
        }
        #pragma unroll
        for (int kt = 0; kt < 8; kt++) {
            uint32_t b[2];
            const __nv_bfloat16* rb = Rt + (nc0 + g) * HSTRIDE + kt * 16 + tq * 2;
            b[0] = *(const uint32_t*)(rb);
            b[1] = *(const uint32_t*)(rb + 8);
            #pragma unroll
            for (int mt = 0; mt < 2; mt++) {
                uint32_t a[4];
                const __nv_bfloat16* xb = Xs + (mt * 16 + g) * HSTRIDE + kt * 16 + tq * 2;
                a[0] = *(const uint32_t*)(xb);
                a[1] = *(const uint32_t*)(xb + 8 * HSTRIDE);
                a[2] = *(const uint32_t*)(xb + 8);
                a[3] = *(const uint32_t*)(xb + 8 * HSTRIDE + 8);
                mma_bf16(sacc[mt], a, b);
            }
        }
        #pragma unroll
        for (int mt = 0; mt < 2; mt++) {
            const int c0 = nc0 + tq * 2;
            const int r0 = mt * 16 + g;
            const int r1 = r0 + 8;
            *(float2*)(SC + r0 * SCSTRIDE + c0) = make_float2(sacc[mt][0], sacc[mt][1]);
            *(float2*)(SC + r1 * SCSTRIDE + c0) = make_float2(sacc[mt][2], sacc[mt][3]);
        }
    }
    __syncthreads();

    // ============ gather + attention (software-pipelined, 2 items) =========
    #pragma unroll
    for (int t = 0; t < ITEM_TILE; t++) {
        const int iv  = iv_[t];
        const int row = wid * ITEM_TILE + t;

        // all adjacency indices up-front
        int eix[S], rix[S];
        #pragma unroll
        for (int q = 0; q < 4; q++) {
            const int4 e = __ldg(&adjE4[iv * 4 + q]);
            const int4 r = __ldg(&adjR4[iv * 4 + q]);
            eix[q*4+0] = e.x; eix[q*4+1] = e.y; eix[q*4+2] = e.z; eix[q*4+3] = e.w;
            rix[q*4+0] = r.x; rix[q*4+1] = r.y; rix[q*4+2] = r.z; rix[q*4+3] = r.w;
        }

        const float4 rp = ent4[(size_t)iv * 32 + lane];

        // all 16 attention factors first (smem reads + MUFU off critical path)
        const float* scr = SC + row * SCSTRIDE;
        float ef[S];
        float sum = 0.f;
        #pragma unroll
        for (int s = 0; s < S; s++) {
            ef[s] = __expf(scr[rix[s]]);   // |p| << 1: no-max-sub validated
            sum += ef[s];
        }

        // two batches of 8: all loads issued before any consumption
        float4 msg = make_float4(0.f, 0.f, 0.f, 0.f);
        #pragma unroll
        for (int h = 0; h < 2; h++) {
            float4 e4b[8];
            #pragma unroll
            for (int s = 0; s < 8; s++)
                e4b[s] = ent4[(size_t)eix[h * 8 + s] * 32 + lane];
            #pragma unroll
            for (int s = 0; s < 8; s++) {
                const float e = ef[h * 8 + s];
                msg.x = fmaf(e, e4b[s].x, msg.x);
                msg.y = fmaf(e, e4b[s].y, msg.y);
                msg.z = fmaf(e, e4b[s].z, msg.z);
                msg.w = fmaf(e, e4b[s].w, msg.w);
            }
        }
        const float inv = __frcp_rn(sum);
        msg.x *= inv; msg.y *= inv; msg.z *= inv; msg.w *= inv;

        uint32_t* xp = (uint32_t*)(Xs + row * HSTRIDE + lane * 4);
        uint32_t* mp = (uint32_t*)(Ms + row * HSTRIDE + lane * 4);
        xp[0] = pack_bf16x2(msg.x + rp.x, msg.y + rp.y);
        xp[1] = pack_bf16x2(msg.z + rp.z, msg.w + rp.w);
        mp[0] = pack_bf16x2(msg.x, msg.y);
        mp[1] = pack_bf16x2(msg.z, msg.w);
    }
    __syncthreads();

    // ================= main GEMM: 2 layers relu(x @ W + b) =================
    const int ncol0 = wid * 8;
    const float bb0 = __ldg(&bias[ncol0 + tq * 2]);
    const float bb1 = __ldg(&bias[ncol0 + tq * 2 + 1]);

    float acc[2][4];

    #pragma unroll
    for (int iter = 0; iter < 2; iter++) {
        #pragma unroll
        for (int mt = 0; mt < 2; mt++) {
            acc[mt][0] = bb0; acc[mt][1] = bb1;
            acc[mt][2] = bb0; acc[mt][3] = bb1;
        }

        #pragma unroll
        for (int kt = 0; kt < 8; kt++) {
            uint32_t b[2];
            const __nv_bfloat16* wb = Wt + (ncol0 + g) * HSTRIDE + kt * 16 + tq * 2;
            b[0] = *(const uint32_t*)(wb);
            b[1] = *(const uint32_t*)(wb + 8);
            #pragma unroll
            for (int mt = 0; mt < 2; mt++) {
                uint32_t a[4];
                const __nv_bfloat16* xb = Xs + (mt * 16 + g) * HSTRIDE + kt * 16 + tq * 2;
                a[0] = *(const uint32_t*)(xb);
                a[1] = *(const uint32_t*)(xb + 8 * HSTRIDE);
                a[2] = *(const uint32_t*)(xb + 8);
                a[3] = *(const uint32_t*)(xb + 8 * HSTRIDE + 8);
                mma_bf16(acc[mt], a, b);
            }
        }

        __syncthreads();

        if (iter == 0) {
            #pragma unroll
            for (int mt = 0; mt < 2; mt++) {
                const int c0 = ncol0 + tq * 2;
                const int r0 = mt * 16 + g;
                const int r1 = r0 + 8;
                const float2 m0 = __bfloat1622float2(*(const __nv_bfloat162*)(Ms + r0 * HSTRIDE + c0));
                const float2 m1 = __bfloat1622float2(*(const __nv_bfloat162*)(Ms + r1 * HSTRIDE + c0));
                *(uint32_t*)(Xs + r0 * HSTRIDE + c0) =
                    pack_bf16x2(m0.x + fmaxf(acc[mt][0], 0.f),
                                m0.y + fmaxf(acc[mt][1], 0.f));
                *(uint32_t*)(Xs + r1 * HSTRIDE + c0) =
                    pack_bf16x2(m1.x + fmaxf(acc[mt][2], 0.f),
                                m1.y + fmaxf(acc[mt][3], 0.f));
            }
            __syncthreads();
        }
    }

    // rep2 = relu(h2) -> Hs fp32 (Wt region; Wt reads done)
    #pragma unroll
    for (int mt = 0; mt < 2; mt++) {
        const int c0 = ncol0 + tq * 2;
        const int r0 = mt * 16 + g;
        const int r1 = r0 + 8;
        *(float2*)(Hs + r0 * FSTRIDE + c0) =
            make_float2(fmaxf(acc[mt][0], 0.f), fmaxf(acc[mt][1], 0.f));
        *(float2*)(Hs + r1 * FSTRIDE + c0) =
            make_float2(fmaxf(acc[mt][2], 0.f), fmaxf(acc[mt][3], 0.f));
    }
    __syncthreads();

    // ================= epilogue: sigmoid(dot(u_emb, rep2)) =================
    #pragma unroll
    for (int t = 0; t < ITEM_TILE; t++) {
        const int item = base + t;
        const int cit  = item < B ? item : (B - 1);
        const float4 uex = usr4[(size_t)u[cit] * 32 + lane];   // L2-hot
        const int row = wid * ITEM_TILE + t;
        const float4 h = *(const float4*)(Hs + row * FSTRIDE + lane * 4);
        float p = uex.x * h.x + uex.y * h.y + uex.z * h.z + uex.w * h.w;
        #pragma unroll
        for (int o = 16; o > 0; o >>= 1)
            p += __shfl_xor_sync(0xffffffffu, p, o);
        if (lane == 0 && item < B)
            out[item] = 1.f / (1.f + __expf(-p));
    }
}

extern "C" void kernel_launch(void* const* d_in, const int* in_sizes, int n_in,
                              void* d_out, int out_size)
{
    const int*   u       = (const int*)d_in[0];
    const int*   v       = (const int*)d_in[1];
    const int*   adj_ent = (const int*)d_in[2];
    const int*   adj_rel = (const int*)d_in[3];
    const float* usr     = (const float*)d_in[4];
    const float* ent     = (const float*)d_in[5];
    const float* rel     = (const float*)d_in[6];
    const float* W       = (const float*)d_in[7];
    const float* bias    = (const float*)d_in[8];
    float* out = (float*)d_out;

    const int B = in_sizes[0];

    static bool attr_set = false;
    if (!attr_set) {
        cudaFuncSetAttribute(kgcn_kernel,
                             cudaFuncAttributeMaxDynamicSharedMemorySize,
                             SMEM_BYTES);
        attr_set = true;
    }

    dim3 grid((B + ITEMS_PB - 1) / ITEMS_PB);   // 256 blocks, 2/SM, 32 warps/SM
    kgcn_kernel<<<grid, BLOCK_THREADS, SMEM_BYTES>>>(
        u, v, adj_ent, adj_rel, usr, ent, rel, W, bias, out, B);
}